// round 7
// baseline (speedup 1.0000x reference)
#include <cuda_runtime.h>

#define NTOK 512
#define DSTATE 192
#define HID 512
#define EMB 1024
#define NEMB 32
#define KC 256
#define CHT 20   // tokens per stage2 chunk (P <= 10 pairs)
#define HSS 20   // smem row stride (floats): 80 B rows, 16B-aligned

// scratch (allocs forbidden -> device globals)
__device__ int g_start[NEMB + 1];
__device__ int g_tokens[NTOK];
__device__ float g_H[NTOK * 4 * HID]; // [slot][m][HID], grouped slot order

struct Params {
    const float* W1[4];
    const float* b1[4];
    const float* W2[4];
    const float* b2[4];
    const float* te[4];
};

// ---------------------------------------------------------------------------
// Stage 1 (fused grouping): each block re-derives the token grouping from the
// raw ids (deterministic rank-scan so every block agrees), block 0 publishes
// it for stage 2, then computes H[slot][m][:] = relu(x_m . W1_m[e] + b1_m[e]).
// Grid: 128 blocks = (e,m), 512 threads = one HID column each.
// ---------------------------------------------------------------------------
template <int L, int OFF>
__device__ __forceinline__ void mlp1(const float* __restrict__ state,
                                     const float* __restrict__ W1,
                                     float b, int m, int s0, int n,
                                     const int* __restrict__ s_tokens,
                                     float* __restrict__ xs) {
    int j = threadIdx.x;
    for (int cb = 0; cb < n; cb += 16) {
        int rem = min(n - cb, 16);
        __syncthreads();
        for (int idx = j; idx < 16 * L; idx += 512) {
            int tk = idx / L, l = idx % L;
            float v = 0.f;
            if (tk < rem) {
                int tok = s_tokens[s0 + cb + tk];
                v = state[tok * DSTATE + OFF + l];
            }
            xs[tk * L + l] = v;
        }
        __syncthreads();

        float acc[16];
        #pragma unroll
        for (int t = 0; t < 16; t++) acc[t] = b;

        #pragma unroll 1
        for (int l0 = 0; l0 < L; l0 += 8) {
            float w[8];
            #pragma unroll
            for (int u = 0; u < 8; u++)
                w[u] = W1[(l0 + u) * HID + j];
            #pragma unroll
            for (int u = 0; u < 8; u++) {
                #pragma unroll
                for (int t = 0; t < 16; t++)
                    acc[t] = fmaf(xs[t * L + l0 + u], w[u], acc[t]);
            }
        }

        #pragma unroll
        for (int t = 0; t < 16; t++) {
            if (t < rem)
                g_H[((size_t)(s0 + cb + t) * 4 + m) * HID + j] = fmaxf(acc[t], 0.f);
        }
        __syncthreads();
    }
}

__global__ void __launch_bounds__(512) k_stage1(const float* __restrict__ state,
                                                const int* __restrict__ ids_raw,
                                                Params p) {
    __shared__ int s_cnt[NEMB];
    __shared__ int s_startA[NEMB + 1];
    __shared__ int s_tokens[NTOK];
    __shared__ int s_i64;
    __shared__ float xs[16 * 64];

    int tid = threadIdx.x; // 512

    if (tid < NEMB) s_cnt[tid] = 0;
    if (tid == 0) s_i64 = 1;
    __syncthreads();
    if (tid < 256 && ids_raw[2 * tid + 1] != 0) s_i64 = 0;
    __syncthreads();
    int myc = s_i64 ? ids_raw[2 * tid] : ids_raw[tid];
    atomicAdd(&s_cnt[myc], 1);
    __syncthreads();
    if (tid <= NEMB) {
        int s = 0;
        for (int jj = 0; jj < tid && jj < NEMB; jj++) s += s_cnt[jj];
        s_startA[tid] = s;
    }
    __syncthreads();
    // deterministic scatter: rank = #earlier tokens with same id (stable).
    s_tokens[tid] = myc;
    __syncthreads();
    int rank = 0;
    for (int t = 0; t < NTOK; t++) {
        int c2 = s_tokens[t];
        if (t < tid && c2 == myc) rank++;
    }
    __syncthreads();
    int slot = s_startA[myc] + rank;
    s_tokens[slot] = tid;
    __syncthreads();

    if (blockIdx.x == 0) {
        if (tid <= NEMB) g_start[tid] = s_startA[tid];
        g_tokens[tid] = s_tokens[tid];
    }

    // ---- per-block MLP
    int m = blockIdx.x & 3;
    int e = blockIdx.x >> 2;
    int s0 = s_startA[e];
    int n  = s_startA[e + 1] - s0;
    if (n == 0) return;

    float b;
    switch (m) {
        case 0: b = p.b1[0][e * HID + tid];
                mlp1<64, 0  >(state, p.W1[0] + (size_t)e * 64 * HID, b, 0, s0, n, s_tokens, xs); break;
        case 1: b = p.b1[1][e * HID + tid];
                mlp1<64, 64 >(state, p.W1[1] + (size_t)e * 64 * HID, b, 1, s0, n, s_tokens, xs); break;
        case 2: b = p.b1[2][e * HID + tid];
                mlp1<32, 128>(state, p.W1[2] + (size_t)e * 32 * HID, b, 2, s0, n, s_tokens, xs); break;
        case 3: b = p.b1[3][e * HID + tid];
                mlp1<32, 160>(state, p.W1[3] + (size_t)e * 32 * HID, b, 3, s0, n, s_tokens, xs); break;
    }
}

// ---------------------------------------------------------------------------
// Kernel 2: out = H . W2[e] + b2[e] + te.
// Block = (256-col tile, m, e); thread owns 2 adjacent columns (LDG.64 W2).
// W2 software-pipelined (double-buffered WD=4 LDG.64 groups). Register diet
// (CHT=20, WD=4, 85-reg cap) -> 6 blocks/SM = 24 warps: occupancy is the
// binding constraint per round-6 profile.
// ---------------------------------------------------------------------------
__device__ __forceinline__ void fma2(unsigned long long& acc,
                                     unsigned long long h2,
                                     unsigned long long w2) {
    asm("fma.rn.f32x2 %0, %1, %2, %0;" : "+l"(acc) : "l"(h2), "l"(w2));
}

#define WD 4  // W2 prefetch group size (LDG.64 each)

template <int P>
__device__ __forceinline__ void consume(const float2* w, const float* hs, int g,
                                        unsigned long long* a0, unsigned long long* a1) {
    #pragma unroll
    for (int j = 0; j < WD; j++) {
        unsigned long long w0, w1;
        asm("mov.b64 %0, {%1,%1};" : "=l"(w0) : "r"(__float_as_uint(w[j].x)));
        asm("mov.b64 %0, {%1,%1};" : "=l"(w1) : "r"(__float_as_uint(w[j].y)));
        const float* hrow = hs + (g + j) * HSS;
        #pragma unroll
        for (int p2 = 0; p2 < P / 2; p2++) {
            ulonglong2 hv = *(const ulonglong2*)(hrow + 4 * p2); // LDS.128 bcast
            fma2(a0[2 * p2],     hv.x, w0);
            fma2(a0[2 * p2 + 1], hv.y, w0);
            fma2(a1[2 * p2],     hv.x, w1);
            fma2(a1[2 * p2 + 1], hv.y, w1);
        }
    }
}

template <int P>  // P even, 2..10: token pairs in flight
__device__ __forceinline__ void run_chunk(
    float* hs, const float* __restrict__ W2ec, const float* __restrict__ Hme,
    float2 init, int s0cb, int rem, int tid, int m, int c0,
    float* __restrict__ out)
{
    unsigned long long a0[P], a1[P];
    unsigned long long i0, i1;
    asm("mov.b64 %0, {%1,%1};" : "=l"(i0) : "r"(__float_as_uint(init.x)));
    asm("mov.b64 %0, {%1,%1};" : "=l"(i1) : "r"(__float_as_uint(init.y)));
    #pragma unroll
    for (int p = 0; p < P; p++) { a0[p] = i0; a1[p] = i1; }

    for (int kc = 0; kc < HID; kc += KC) {
        __syncthreads();
        // stage h transposed: hs[kk*HSS + tk], tk in [0, 2P)
        #pragma unroll
        for (int tk = 0; tk < 2 * P; tk++) {
            int slot = min(s0cb + tk, NTOK - 1); // clamp pad (discarded later)
            const float* src = Hme + (size_t)slot * (4 * HID) + kc;
            #pragma unroll
            for (int kk = 0; kk < KC; kk += 128)
                hs[(kk + tid) * HSS + tk] = src[kk + tid];
        }
        __syncthreads();

        const float* wp = W2ec + (size_t)kc * EMB;
        float2 wA[WD], wB[WD];

        #pragma unroll
        for (int j = 0; j < WD; j++)
            wA[j] = __ldcs((const float2*)(wp + (size_t)j * EMB));

        #pragma unroll 1
        for (int g = 0; g < KC - 2 * WD; g += 2 * WD) {
            #pragma unroll
            for (int j = 0; j < WD; j++)
                wB[j] = __ldcs((const float2*)(wp + (size_t)(g + WD + j) * EMB));
            consume<P>(wA, hs, g, a0, a1);
            #pragma unroll
            for (int j = 0; j < WD; j++)
                wA[j] = __ldcs((const float2*)(wp + (size_t)(g + 2 * WD + j) * EMB));
            consume<P>(wB, hs, g + WD, a0, a1);
        }
        // tail: groups KC-2*WD and KC-WD
        #pragma unroll
        for (int j = 0; j < WD; j++)
            wB[j] = __ldcs((const float2*)(wp + (size_t)(KC - WD + j) * EMB));
        consume<P>(wA, hs, KC - 2 * WD, a0, a1);
        consume<P>(wB, hs, KC - WD, a0, a1);
    }

    #pragma unroll
    for (int p = 0; p < P; p++) {
        float2 vA = *(float2*)&a0[p]; // col c0:   (tok 2p, tok 2p+1)
        float2 vB = *(float2*)&a1[p]; // col c0+1
        int t0 = 2 * p;
        if (t0 < rem) {
            int tok = g_tokens[s0cb + t0];
            *(float2*)&out[((size_t)tok * 4 + m) * EMB + c0] = make_float2(vA.x, vB.x);
        }
        if (t0 + 1 < rem) {
            int tok = g_tokens[s0cb + t0 + 1];
            *(float2*)&out[((size_t)tok * 4 + m) * EMB + c0] = make_float2(vA.y, vB.y);
        }
    }
}

__global__ void __launch_bounds__(128, 6) k_stage2(Params p, float* __restrict__ out) {
    int tile = blockIdx.x; // 0..3 (256 cols each)
    int m    = blockIdx.y; // 0..3
    int e    = blockIdx.z; // 0..31
    int s0 = g_start[e];
    int n  = g_start[e + 1] - s0;
    if (n == 0) return;

    int tid = threadIdx.x;
    int c0 = tile * 256 + tid * 2;
    const float* __restrict__ W2ec = p.W2[m] + (size_t)e * HID * EMB + c0;
    const float* __restrict__ Hme  = g_H + m * HID;
    float2 init = make_float2(p.b2[m][e * EMB + c0]     + p.te[m][c0],
                              p.b2[m][e * EMB + c0 + 1] + p.te[m][c0 + 1]);

    __shared__ __align__(16) float hs[KC * HSS];

    for (int cb = 0; cb < n; cb += CHT) {
        int rem = min(n - cb, CHT);
        int pairsEven = ((rem + 3) >> 2) << 1; // even ceil(rem/2)
        int s0cb = s0 + cb;
        switch (pairsEven) {
#define CASE(PP) case PP: run_chunk<PP>(hs, W2ec, Hme, init, s0cb, rem, tid, m, c0, out); break;
            CASE(2) CASE(4) CASE(6) CASE(8) CASE(10)
#undef CASE
        }
    }
}

// ---------------------------------------------------------------------------
extern "C" void kernel_launch(void* const* d_in, const int* in_sizes, int n_in,
                              void* d_out, int out_size) {
    const float* state = (const float*)d_in[0];
    const int*   ids   = (const int*)d_in[1];

    Params P;
    int base = 2;
    for (int m = 0; m < 4; m++) {
        P.W1[m] = (const float*)d_in[base + 0];
        P.b1[m] = (const float*)d_in[base + 1];
        P.W2[m] = (const float*)d_in[base + 2];
        P.b2[m] = (const float*)d_in[base + 3];
        P.te[m] = (const float*)d_in[base + 4];
        base += 5;
    }
    float* out = (float*)d_out;

    k_stage1<<<128, 512>>>(state, ids, P);
    k_stage2<<<dim3(4, 4, 32), 128>>>(P, out);
}

// round 8
// speedup vs baseline: 2.7896x; 2.7896x over previous
#include <cuda_runtime.h>

#define NTOK 512
#define DSTATE 192
#define HID 512
#define EMB 1024
#define NEMB 32
#define KC 256   // K rows per stage2 block (HID / 2 k-halves)
#define CHT 24   // tokens per stage2 chunk (P <= 12 pairs)
#define HSS 28   // smem row stride (floats): 112 B rows, 16B-aligned

// scratch (allocs forbidden -> device globals)
__device__ int g_start[NEMB + 1];
__device__ int g_tokens[NTOK];
__device__ float g_H[NTOK * 4 * HID];        // [slot][m][HID]
__device__ float g_part[2][4 * NTOK * EMB];  // [kh][m][slot][EMB]

struct Params {
    const float* W1[4];
    const float* b1[4];
    const float* W2[4];
    const float* b2[4];
    const float* te[4];
};

// ---------------------------------------------------------------------------
// Stage 1 (fused grouping): each block re-derives the token grouping from the
// raw ids (deterministic rank-scan so every block agrees), block 0 publishes
// it for stage 2, then computes H[slot][m][:] = relu(x_m . W1_m[e] + b1_m[e]).
// Grid: 128 blocks = (e,m), 512 threads = one HID column each.
// ---------------------------------------------------------------------------
template <int L, int OFF>
__device__ __forceinline__ void mlp1(const float* __restrict__ state,
                                     const float* __restrict__ W1,
                                     float b, int m, int s0, int n,
                                     const int* __restrict__ s_tokens,
                                     float* __restrict__ xs) {
    int j = threadIdx.x;
    for (int cb = 0; cb < n; cb += 16) {
        int rem = min(n - cb, 16);
        __syncthreads();
        for (int idx = j; idx < 16 * L; idx += 512) {
            int tk = idx / L, l = idx % L;
            float v = 0.f;
            if (tk < rem) {
                int tok = s_tokens[s0 + cb + tk];
                v = state[tok * DSTATE + OFF + l];
            }
            xs[tk * L + l] = v;
        }
        __syncthreads();

        float acc[16];
        #pragma unroll
        for (int t = 0; t < 16; t++) acc[t] = b;

        #pragma unroll 1
        for (int l0 = 0; l0 < L; l0 += 8) {
            float w[8];
            #pragma unroll
            for (int u = 0; u < 8; u++)
                w[u] = W1[(l0 + u) * HID + j];
            #pragma unroll
            for (int u = 0; u < 8; u++) {
                #pragma unroll
                for (int t = 0; t < 16; t++)
                    acc[t] = fmaf(xs[t * L + l0 + u], w[u], acc[t]);
            }
        }

        #pragma unroll
        for (int t = 0; t < 16; t++) {
            if (t < rem)
                g_H[((size_t)(s0 + cb + t) * 4 + m) * HID + j] = fmaxf(acc[t], 0.f);
        }
        __syncthreads();
    }
}

__global__ void __launch_bounds__(512) k_stage1(const float* __restrict__ state,
                                                const int* __restrict__ ids_raw,
                                                Params p) {
    __shared__ int s_cnt[NEMB];
    __shared__ int s_startA[NEMB + 1];
    __shared__ int s_tokens[NTOK];
    __shared__ int s_i64;
    __shared__ float xs[16 * 64];

    int tid = threadIdx.x; // 512

    if (tid < NEMB) s_cnt[tid] = 0;
    if (tid == 0) s_i64 = 1;
    __syncthreads();
    if (tid < 256 && ids_raw[2 * tid + 1] != 0) s_i64 = 0;
    __syncthreads();
    int myc = s_i64 ? ids_raw[2 * tid] : ids_raw[tid];
    atomicAdd(&s_cnt[myc], 1);
    __syncthreads();
    if (tid <= NEMB) {
        int s = 0;
        for (int jj = 0; jj < tid && jj < NEMB; jj++) s += s_cnt[jj];
        s_startA[tid] = s;
    }
    __syncthreads();
    // deterministic scatter: rank = #earlier tokens with same id (stable).
    s_tokens[tid] = myc;
    __syncthreads();
    int rank = 0;
    for (int t = 0; t < NTOK; t++) {
        int c2 = s_tokens[t];
        if (t < tid && c2 == myc) rank++;
    }
    __syncthreads();
    int slot = s_startA[myc] + rank;
    s_tokens[slot] = tid;
    __syncthreads();

    if (blockIdx.x == 0) {
        if (tid <= NEMB) g_start[tid] = s_startA[tid];
        g_tokens[tid] = s_tokens[tid];
    }

    // ---- per-block MLP
    int m = blockIdx.x & 3;
    int e = blockIdx.x >> 2;
    int s0 = s_startA[e];
    int n  = s_startA[e + 1] - s0;
    if (n == 0) return;

    float b;
    switch (m) {
        case 0: b = p.b1[0][e * HID + tid];
                mlp1<64, 0  >(state, p.W1[0] + (size_t)e * 64 * HID, b, 0, s0, n, s_tokens, xs); break;
        case 1: b = p.b1[1][e * HID + tid];
                mlp1<64, 64 >(state, p.W1[1] + (size_t)e * 64 * HID, b, 1, s0, n, s_tokens, xs); break;
        case 2: b = p.b1[2][e * HID + tid];
                mlp1<32, 128>(state, p.W1[2] + (size_t)e * 32 * HID, b, 2, s0, n, s_tokens, xs); break;
        case 3: b = p.b1[3][e * HID + tid];
                mlp1<32, 160>(state, p.W1[3] + (size_t)e * 32 * HID, b, 3, s0, n, s_tokens, xs); break;
    }
}

// ---------------------------------------------------------------------------
// Stage 2 (K-split): part[kh][m][slot][c] = H[slot][m][kh*256:+256] . W2rows.
// Block = (kh, 256-col tile, m, e); thread owns 2 adjacent columns (LDG.64).
// Round-6 proven body: WD=8 double-buffered register pipeline, CHT=24,
// launch_bounds(128,4). Grid = 1024 blocks to lift grid-limited occupancy.
// ---------------------------------------------------------------------------
__device__ __forceinline__ void fma2(unsigned long long& acc,
                                     unsigned long long h2,
                                     unsigned long long w2) {
    asm("fma.rn.f32x2 %0, %1, %2, %0;" : "+l"(acc) : "l"(h2), "l"(w2));
}

#define WD 8  // W2 prefetch group size (LDG.64 each -> 16 lines/warp)

template <int P>
__device__ __forceinline__ void consume(const float2* w, const float* hs, int g,
                                        unsigned long long* a0, unsigned long long* a1) {
    #pragma unroll
    for (int j = 0; j < WD; j++) {
        unsigned long long w0, w1;
        asm("mov.b64 %0, {%1,%1};" : "=l"(w0) : "r"(__float_as_uint(w[j].x)));
        asm("mov.b64 %0, {%1,%1};" : "=l"(w1) : "r"(__float_as_uint(w[j].y)));
        const float* hrow = hs + (g + j) * HSS;
        #pragma unroll
        for (int p2 = 0; p2 < P / 2; p2++) {
            ulonglong2 hv = *(const ulonglong2*)(hrow + 4 * p2); // LDS.128 bcast
            fma2(a0[2 * p2],     hv.x, w0);
            fma2(a0[2 * p2 + 1], hv.y, w0);
            fma2(a1[2 * p2],     hv.x, w1);
            fma2(a1[2 * p2 + 1], hv.y, w1);
        }
    }
}

template <int P>  // P even, 2..12: token pairs in flight
__device__ __forceinline__ void run_chunk(
    float* hs, const float* __restrict__ W2ec, const float* __restrict__ Hme,
    float2 init, int s0cb, int rem, int tid, int c0,
    float* __restrict__ pm)  // part base for this (kh,m): index slot*EMB + c
{
    unsigned long long a0[P], a1[P];
    unsigned long long i0, i1;
    asm("mov.b64 %0, {%1,%1};" : "=l"(i0) : "r"(__float_as_uint(init.x)));
    asm("mov.b64 %0, {%1,%1};" : "=l"(i1) : "r"(__float_as_uint(init.y)));
    #pragma unroll
    for (int p = 0; p < P; p++) { a0[p] = i0; a1[p] = i1; }

    __syncthreads();
    // stage h transposed: hs[kk*HSS + tk], tk in [0, 2P); Hme pre-offset kh*KC
    #pragma unroll
    for (int tk = 0; tk < 2 * P; tk++) {
        int slot = min(s0cb + tk, NTOK - 1); // clamp pad (discarded later)
        const float* src = Hme + (size_t)slot * (4 * HID);
        #pragma unroll
        for (int kk = 0; kk < KC; kk += 128)
            hs[(kk + tid) * HSS + tk] = src[kk + tid];
    }
    __syncthreads();

    float2 wA[WD], wB[WD];
    #pragma unroll
    for (int j = 0; j < WD; j++)
        wA[j] = __ldcs((const float2*)(W2ec + (size_t)j * EMB));

    #pragma unroll 1
    for (int g = 0; g < KC - 2 * WD; g += 2 * WD) {
        #pragma unroll
        for (int j = 0; j < WD; j++)
            wB[j] = __ldcs((const float2*)(W2ec + (size_t)(g + WD + j) * EMB));
        consume<P>(wA, hs, g, a0, a1);
        #pragma unroll
        for (int j = 0; j < WD; j++)
            wA[j] = __ldcs((const float2*)(W2ec + (size_t)(g + 2 * WD + j) * EMB));
        consume<P>(wB, hs, g + WD, a0, a1);
    }
    #pragma unroll
    for (int j = 0; j < WD; j++)
        wB[j] = __ldcs((const float2*)(W2ec + (size_t)(KC - WD + j) * EMB));
    consume<P>(wA, hs, KC - 2 * WD, a0, a1);
    consume<P>(wB, hs, KC - WD, a0, a1);

    #pragma unroll
    for (int p = 0; p < P; p++) {
        float2 vA = *(float2*)&a0[p]; // col c0:   (tok 2p, tok 2p+1)
        float2 vB = *(float2*)&a1[p]; // col c0+1
        int t0 = 2 * p;
        if (t0 < rem) {
            int slot = s0cb + t0;
            *(float2*)&pm[(size_t)slot * EMB + c0] = make_float2(vA.x, vB.x);
        }
        if (t0 + 1 < rem) {
            int slot = s0cb + t0 + 1;
            *(float2*)&pm[(size_t)slot * EMB + c0] = make_float2(vA.y, vB.y);
        }
    }
}

__global__ void __launch_bounds__(128, 4) k_stage2(Params p) {
    int bx   = blockIdx.x;     // 0..7 = tile(0..3) | kh<<2
    int tile = bx & 3;
    int kh   = bx >> 2;        // k-half: W2 rows [kh*256, +256)
    int m    = blockIdx.y;     // 0..3
    int e    = blockIdx.z;     // 0..31
    int s0 = g_start[e];
    int n  = g_start[e + 1] - s0;
    if (n == 0) return;

    int tid = threadIdx.x;
    int c0 = tile * 256 + tid * 2;
    const float* __restrict__ W2ec = p.W2[m] + (size_t)e * HID * EMB
                                   + (size_t)kh * KC * EMB + c0;
    const float* __restrict__ Hme  = g_H + m * HID + kh * KC;
    float2 init = (kh == 0)
        ? make_float2(p.b2[m][e * EMB + c0]     + p.te[m][c0],
                      p.b2[m][e * EMB + c0 + 1] + p.te[m][c0 + 1])
        : make_float2(0.f, 0.f);
    float* pm = &g_part[kh][(size_t)m * NTOK * EMB];

    __shared__ __align__(16) float hs[KC * HSS];

    for (int cb = 0; cb < n; cb += CHT) {
        int rem = min(n - cb, CHT);
        int pairsEven = ((rem + 3) >> 2) << 1; // even ceil(rem/2)
        int s0cb = s0 + cb;
        switch (pairsEven) {
#define CASE(PP) case PP: run_chunk<PP>(hs, W2ec, Hme, init, s0cb, rem, tid, c0, pm); break;
            CASE(2) CASE(4) CASE(6) CASE(8) CASE(10) CASE(12)
#undef CASE
        }
    }
}

// ---------------------------------------------------------------------------
// Combine: out[tok][m][c] = part0 + part1, gathering slot -> token.
// Grid: (512 slots, 4 m), 256 threads, one float4 per thread.
// ---------------------------------------------------------------------------
__global__ void __launch_bounds__(256) k_combine(float* __restrict__ out) {
    int slot = blockIdx.x;
    int m    = blockIdx.y;
    int tid  = threadIdx.x;
    int tok  = g_tokens[slot];
    const float4* p0 = (const float4*)(&g_part[0][0] + ((size_t)m * NTOK + slot) * EMB);
    const float4* p1 = (const float4*)(&g_part[1][0] + ((size_t)m * NTOK + slot) * EMB);
    float4* o = (float4*)(out + ((size_t)tok * 4 + m) * EMB);
    float4 a = p0[tid], b = p1[tid];
    o[tid] = make_float4(a.x + b.x, a.y + b.y, a.z + b.z, a.w + b.w);
}

// ---------------------------------------------------------------------------
extern "C" void kernel_launch(void* const* d_in, const int* in_sizes, int n_in,
                              void* d_out, int out_size) {
    const float* state = (const float*)d_in[0];
    const int*   ids   = (const int*)d_in[1];

    Params P;
    int base = 2;
    for (int m = 0; m < 4; m++) {
        P.W1[m] = (const float*)d_in[base + 0];
        P.b1[m] = (const float*)d_in[base + 1];
        P.W2[m] = (const float*)d_in[base + 2];
        P.b2[m] = (const float*)d_in[base + 3];
        P.te[m] = (const float*)d_in[base + 4];
        base += 5;
    }
    float* out = (float*)d_out;

    k_stage1<<<128, 512>>>(state, ids, P);
    k_stage2<<<dim3(8, 4, 32), 128>>>(P);
    k_combine<<<dim3(NTOK, 4), 256>>>(out);
}

// round 9
// speedup vs baseline: 3.0579x; 1.0962x over previous
#include <cuda_runtime.h>

#define NTOK 512
#define DSTATE 192
#define HID 512
#define EMB 1024
#define NEMB 32
#define KC 256   // K rows per stage2 block (HID / 2 k-halves)
#define CHT 24   // tokens per stage2 chunk (P <= 12 pairs)
#define HSS 28   // smem row stride (floats): 112 B rows, 16B-aligned

// scratch (allocs forbidden -> device globals)
__device__ int g_start[NEMB + 1];
__device__ int g_tokens[NTOK];
__device__ float g_H[NTOK * 4 * HID];        // [slot][m][HID]
__device__ float g_part[2][4 * NTOK * EMB];  // [kh][m][slot][EMB]

struct Params {
    const float* W1[4];
    const float* b1[4];
    const float* W2[4];
    const float* b2[4];
    const float* te[4];
};

// ---------------------------------------------------------------------------
// Stage 1 (fused grouping): each block derives the token grouping from the
// raw ids with a deterministic match/histogram scheme (input-dependent only,
// so every block agrees), block 0 publishes it for stage 2, then computes
// H[slot][m][:] = relu(x_m . W1_m[e] + b1_m[e]).
// Grid: 128 blocks = (e,m), 512 threads = one HID column each.
// ---------------------------------------------------------------------------
template <int L, int OFF>
__device__ __forceinline__ void mlp1(const float* __restrict__ state,
                                     const float* __restrict__ W1,
                                     float b, int m, int s0, int n,
                                     const int* __restrict__ s_tokens,
                                     float* __restrict__ xs) {
    int j = threadIdx.x;
    for (int cb = 0; cb < n; cb += 16) {
        int rem = min(n - cb, 16);
        __syncthreads();
        for (int idx = j; idx < 16 * L; idx += 512) {
            int tk = idx / L, l = idx % L;
            float v = 0.f;
            if (tk < rem) {
                int tok = s_tokens[s0 + cb + tk];
                v = state[tok * DSTATE + OFF + l];
            }
            xs[tk * L + l] = v;
        }
        __syncthreads();

        float acc[16];
        #pragma unroll
        for (int t = 0; t < 16; t++) acc[t] = b;

        #pragma unroll 1
        for (int l0 = 0; l0 < L; l0 += 8) {
            float w[8];
            #pragma unroll
            for (int u = 0; u < 8; u++)
                w[u] = W1[(l0 + u) * HID + j];
            #pragma unroll
            for (int u = 0; u < 8; u++) {
                #pragma unroll
                for (int t = 0; t < 16; t++)
                    acc[t] = fmaf(xs[t * L + l0 + u], w[u], acc[t]);
            }
        }

        #pragma unroll
        for (int t = 0; t < 16; t++) {
            if (t < rem)
                g_H[((size_t)(s0 + cb + t) * 4 + m) * HID + j] = fmaxf(acc[t], 0.f);
        }
        __syncthreads();
    }
}

__global__ void __launch_bounds__(512) k_stage1(const float* __restrict__ state,
                                                const int* __restrict__ ids_raw,
                                                Params p) {
    __shared__ int s_startA[NEMB + 1];
    __shared__ int s_tokens[NTOK];
    __shared__ int s_wcnt[16 * NEMB];  // per-warp id histogram
    __shared__ int s_woff[16 * NEMB];  // exclusive prefix over warps
    __shared__ int s_i64;
    __shared__ float xs[16 * 64];

    int tid  = threadIdx.x; // 512
    int warp = tid >> 5, lane = tid & 31;

    s_wcnt[tid & (16 * NEMB - 1)] = 0;
    if (tid == 0) s_i64 = 1;
    __syncthreads();
    if (tid < 256 && ids_raw[2 * tid + 1] != 0) s_i64 = 0;
    __syncthreads();
    int myc = s_i64 ? ids_raw[2 * tid] : ids_raw[tid];

    // deterministic grouping via warp match + per-warp histogram prefix
    unsigned same = __match_any_sync(0xffffffffu, myc);
    int rankw = __popc(same & ((1u << lane) - 1u));
    if (rankw == 0) s_wcnt[warp * NEMB + myc] = __popc(same);
    __syncthreads();

    if (tid < NEMB) {
        int sum = 0;
        #pragma unroll
        for (int w = 0; w < 16; w++) {
            int ccc = s_wcnt[w * NEMB + tid];
            s_woff[w * NEMB + tid] = sum;
            sum += ccc;
        }
        s_wcnt[tid] = sum; // reuse row 0 as total count per id (after loop)
    }
    __syncthreads();
    if (tid <= NEMB) {
        int s = 0;
        for (int jj = 0; jj < tid && jj < NEMB; jj++) s += s_wcnt[jj];
        s_startA[tid] = s;
    }
    __syncthreads();

    int slot = s_startA[myc] + s_woff[warp * NEMB + myc] + rankw;
    s_tokens[slot] = tid;
    __syncthreads();

    if (blockIdx.x == 0) {
        if (tid <= NEMB) g_start[tid] = s_startA[tid];
        g_tokens[tid] = s_tokens[tid];
    }

    // ---- per-block MLP
    int m = blockIdx.x & 3;
    int e = blockIdx.x >> 2;
    int s0 = s_startA[e];
    int n  = s_startA[e + 1] - s0;
    if (n == 0) return;

    float b;
    switch (m) {
        case 0: b = p.b1[0][e * HID + tid];
                mlp1<64, 0  >(state, p.W1[0] + (size_t)e * 64 * HID, b, 0, s0, n, s_tokens, xs); break;
        case 1: b = p.b1[1][e * HID + tid];
                mlp1<64, 64 >(state, p.W1[1] + (size_t)e * 64 * HID, b, 1, s0, n, s_tokens, xs); break;
        case 2: b = p.b1[2][e * HID + tid];
                mlp1<32, 128>(state, p.W1[2] + (size_t)e * 32 * HID, b, 2, s0, n, s_tokens, xs); break;
        case 3: b = p.b1[3][e * HID + tid];
                mlp1<32, 160>(state, p.W1[3] + (size_t)e * 32 * HID, b, 3, s0, n, s_tokens, xs); break;
    }
}

// ---------------------------------------------------------------------------
// Stage 2 (K-split): part[kh][m][slot][c] = H[slot][m][kh*256:+256] . W2rows.
// Block = (kh, 256-col tile, m, e); thread owns 2 adjacent columns (LDG.64).
// WD=8 double-buffered register pipeline, CHT=24, launch_bounds(128,4).
// ---------------------------------------------------------------------------
__device__ __forceinline__ void fma2(unsigned long long& acc,
                                     unsigned long long h2,
                                     unsigned long long w2) {
    asm("fma.rn.f32x2 %0, %1, %2, %0;" : "+l"(acc) : "l"(h2), "l"(w2));
}

#define WD 8  // W2 prefetch group size (LDG.64 each -> 16 lines/warp)

template <int P>
__device__ __forceinline__ void consume(const float2* w, const float* hs, int g,
                                        unsigned long long* a0, unsigned long long* a1) {
    #pragma unroll
    for (int j = 0; j < WD; j++) {
        unsigned long long w0, w1;
        asm("mov.b64 %0, {%1,%1};" : "=l"(w0) : "r"(__float_as_uint(w[j].x)));
        asm("mov.b64 %0, {%1,%1};" : "=l"(w1) : "r"(__float_as_uint(w[j].y)));
        const float* hrow = hs + (g + j) * HSS;
        #pragma unroll
        for (int p2 = 0; p2 < P / 2; p2++) {
            ulonglong2 hv = *(const ulonglong2*)(hrow + 4 * p2); // LDS.128 bcast
            fma2(a0[2 * p2],     hv.x, w0);
            fma2(a0[2 * p2 + 1], hv.y, w0);
            fma2(a1[2 * p2],     hv.x, w1);
            fma2(a1[2 * p2 + 1], hv.y, w1);
        }
    }
}

template <int P>  // P even, 2..12: token pairs in flight
__device__ __forceinline__ void run_chunk(
    float* hs, const float* __restrict__ W2ec, const float* __restrict__ Hme,
    float2 init, int s0cb, int rem, int tid, int c0,
    float* __restrict__ pm)  // part base for this (kh,m): index slot*EMB + c
{
    unsigned long long a0[P], a1[P];
    unsigned long long i0, i1;
    asm("mov.b64 %0, {%1,%1};" : "=l"(i0) : "r"(__float_as_uint(init.x)));
    asm("mov.b64 %0, {%1,%1};" : "=l"(i1) : "r"(__float_as_uint(init.y)));
    #pragma unroll
    for (int p = 0; p < P; p++) { a0[p] = i0; a1[p] = i1; }

    __syncthreads();
    // stage h transposed: hs[kk*HSS + tk], tk in [0, 2P); Hme pre-offset kh*KC
    #pragma unroll
    for (int tk = 0; tk < 2 * P; tk++) {
        int slot = min(s0cb + tk, NTOK - 1); // clamp pad (discarded later)
        const float* src = Hme + (size_t)slot * (4 * HID);
        #pragma unroll
        for (int kk = 0; kk < KC; kk += 128)
            hs[(kk + tid) * HSS + tk] = src[kk + tid];
    }
    __syncthreads();

    float2 wA[WD], wB[WD];
    #pragma unroll
    for (int j = 0; j < WD; j++)
        wA[j] = __ldcs((const float2*)(W2ec + (size_t)j * EMB));

    #pragma unroll 1
    for (int g = 0; g < KC - 2 * WD; g += 2 * WD) {
        #pragma unroll
        for (int j = 0; j < WD; j++)
            wB[j] = __ldcs((const float2*)(W2ec + (size_t)(g + WD + j) * EMB));
        consume<P>(wA, hs, g, a0, a1);
        #pragma unroll
        for (int j = 0; j < WD; j++)
            wA[j] = __ldcs((const float2*)(W2ec + (size_t)(g + 2 * WD + j) * EMB));
        consume<P>(wB, hs, g + WD, a0, a1);
    }
    #pragma unroll
    for (int j = 0; j < WD; j++)
        wB[j] = __ldcs((const float2*)(W2ec + (size_t)(KC - WD + j) * EMB));
    consume<P>(wA, hs, KC - 2 * WD, a0, a1);
    consume<P>(wB, hs, KC - WD, a0, a1);

    #pragma unroll
    for (int p = 0; p < P; p++) {
        float2 vA = *(float2*)&a0[p]; // col c0:   (tok 2p, tok 2p+1)
        float2 vB = *(float2*)&a1[p]; // col c0+1
        int t0 = 2 * p;
        if (t0 < rem) {
            int slot = s0cb + t0;
            *(float2*)&pm[(size_t)slot * EMB + c0] = make_float2(vA.x, vB.x);
        }
        if (t0 + 1 < rem) {
            int slot = s0cb + t0 + 1;
            *(float2*)&pm[(size_t)slot * EMB + c0] = make_float2(vA.y, vB.y);
        }
    }
}

__global__ void __launch_bounds__(128, 4) k_stage2(Params p) {
    int bx   = blockIdx.x;     // 0..7 = tile(0..3) | kh<<2
    int tile = bx & 3;
    int kh   = bx >> 2;        // k-half: W2 rows [kh*256, +256)
    int m    = blockIdx.y;     // 0..3
    int e    = blockIdx.z;     // 0..31
    int s0 = g_start[e];
    int n  = g_start[e + 1] - s0;
    if (n == 0) return;

    int tid = threadIdx.x;
    int c0 = tile * 256 + tid * 2;
    const float* __restrict__ W2ec = p.W2[m] + (size_t)e * HID * EMB
                                   + (size_t)kh * KC * EMB + c0;
    const float* __restrict__ Hme  = g_H + m * HID + kh * KC;
    float2 init = (kh == 0)
        ? make_float2(p.b2[m][e * EMB + c0]     + p.te[m][c0],
                      p.b2[m][e * EMB + c0 + 1] + p.te[m][c0 + 1])
        : make_float2(0.f, 0.f);
    float* pm = &g_part[kh][(size_t)m * NTOK * EMB];

    __shared__ __align__(16) float hs[KC * HSS];

    for (int cb = 0; cb < n; cb += CHT) {
        int rem = min(n - cb, CHT);
        int pairsEven = ((rem + 3) >> 2) << 1; // even ceil(rem/2)
        int s0cb = s0 + cb;
        switch (pairsEven) {
#define CASE(PP) case PP: run_chunk<PP>(hs, W2ec, Hme, init, s0cb, rem, tid, c0, pm); break;
            CASE(2) CASE(4) CASE(6) CASE(8) CASE(10) CASE(12)
#undef CASE
        }
    }
}

// ---------------------------------------------------------------------------
// Combine: out[tok][m][c] = part0 + part1, gathering slot -> token.
// Grid: (512 slots, 4 m), 256 threads, one float4 per thread.
// ---------------------------------------------------------------------------
__global__ void __launch_bounds__(256) k_combine(float* __restrict__ out) {
    int slot = blockIdx.x;
    int m    = blockIdx.y;
    int tid  = threadIdx.x;
    int tok  = g_tokens[slot];
    const float4* p0 = (const float4*)(&g_part[0][0] + ((size_t)m * NTOK + slot) * EMB);
    const float4* p1 = (const float4*)(&g_part[1][0] + ((size_t)m * NTOK + slot) * EMB);
    float4* o = (float4*)(out + ((size_t)tok * 4 + m) * EMB);
    float4 a = p0[tid], b = p1[tid];
    o[tid] = make_float4(a.x + b.x, a.y + b.y, a.z + b.z, a.w + b.w);
}

// ---------------------------------------------------------------------------
extern "C" void kernel_launch(void* const* d_in, const int* in_sizes, int n_in,
                              void* d_out, int out_size) {
    const float* state = (const float*)d_in[0];
    const int*   ids   = (const int*)d_in[1];

    Params P;
    int base = 2;
    for (int m = 0; m < 4; m++) {
        P.W1[m] = (const float*)d_in[base + 0];
        P.b1[m] = (const float*)d_in[base + 1];
        P.W2[m] = (const float*)d_in[base + 2];
        P.b2[m] = (const float*)d_in[base + 3];
        P.te[m] = (const float*)d_in[base + 4];
        base += 5;
    }
    float* out = (float*)d_out;

    k_stage1<<<128, 512>>>(state, ids, P);
    k_stage2<<<dim3(8, 4, 32), 128>>>(P);
    k_combine<<<dim3(NTOK, 4), 256>>>(out);
}

// round 10
// speedup vs baseline: 3.0654x; 1.0025x over previous
#include <cuda_runtime.h>

#define NTOK 512
#define DSTATE 192
#define HID 512
#define EMB 1024
#define NEMB 32
#define KC 256   // K rows per fused block (HID / 2 k-halves)
#define CHT 24   // tokens per chunk (P <= 12 pairs)
#define HSS 28   // hs row stride (floats): 112 B rows, 16B-aligned
#define XSS 28   // xs row stride (floats): 16B-aligned (112 = 16*7)

// scratch (allocs forbidden -> device globals)
__device__ int g_start[NEMB + 1];
__device__ int g_tokens[NTOK];
__device__ float g_part[2][4 * NTOK * EMB];  // [kh][m][slot][EMB]

struct Params {
    const float* W1[4];
    const float* b1[4];
    const float* W2[4];
    const float* b2[4];
    const float* te[4];
};

// ---------------------------------------------------------------------------
// Grouping: 1 block, 512 threads. Deterministic (input-only) match/histogram.
// ---------------------------------------------------------------------------
__global__ void __launch_bounds__(512) k_group(const int* __restrict__ ids_raw) {
    __shared__ int s_wcnt[16 * NEMB];
    __shared__ int s_woff[16 * NEMB];
    __shared__ int s_start[NEMB + 1];
    __shared__ int s_i64;

    int tid  = threadIdx.x;
    int warp = tid >> 5, lane = tid & 31;

    s_wcnt[tid] = 0;
    if (tid == 0) s_i64 = 1;
    __syncthreads();
    // int64 ids (<32) have zero high words at odd int32 indices.
    if (tid < 256 && ids_raw[2 * tid + 1] != 0) s_i64 = 0;
    __syncthreads();
    int myc = s_i64 ? ids_raw[2 * tid] : ids_raw[tid];

    unsigned same = __match_any_sync(0xffffffffu, myc);
    int rankw = __popc(same & ((1u << lane) - 1u));
    if (rankw == 0) s_wcnt[warp * NEMB + myc] = __popc(same);
    __syncthreads();

    if (tid < NEMB) {
        int sum = 0;
        #pragma unroll
        for (int w = 0; w < 16; w++) {
            int c = s_wcnt[w * NEMB + tid];
            s_woff[w * NEMB + tid] = sum;
            sum += c;
        }
        s_wcnt[tid] = sum; // total per id
    }
    __syncthreads();
    if (tid <= NEMB) {
        int s = 0;
        for (int j = 0; j < tid && j < NEMB; j++) s += s_wcnt[j];
        s_start[tid] = s;
        g_start[tid] = s;
    }
    __syncthreads();

    int slot = s_start[myc] + s_woff[warp * NEMB + myc] + rankw;
    g_tokens[slot] = tid;
}

// ---------------------------------------------------------------------------
// Fused kernel: per block (kh, tile, m, e):
//   prologue: h[kk][tk] = relu(x . W1half + b1) computed straight into smem
//   mainloop: stream W2 half (double-buffered LDG.64), f32x2 accumulate
//   epilogue: partials to g_part[kh][m][slot][:]
// ---------------------------------------------------------------------------
__device__ __forceinline__ void fma2(unsigned long long& acc,
                                     unsigned long long h2,
                                     unsigned long long w2) {
    asm("fma.rn.f32x2 %0, %1, %2, %0;" : "+l"(acc) : "l"(h2), "l"(w2));
}
__device__ __forceinline__ unsigned long long splat2(float v) {
    unsigned long long r;
    asm("mov.b64 %0, {%1,%1};" : "=l"(r) : "r"(__float_as_uint(v)));
    return r;
}

#define WD 8  // W2 prefetch group size (LDG.64 each -> 16 lines/warp)

template <int P>
__device__ __forceinline__ void consume(const float2* w, const float* hs, int g,
                                        unsigned long long* a0, unsigned long long* a1) {
    #pragma unroll
    for (int j = 0; j < WD; j++) {
        unsigned long long w0 = splat2(w[j].x);
        unsigned long long w1 = splat2(w[j].y);
        const float* hrow = hs + (g + j) * HSS;
        #pragma unroll
        for (int p2 = 0; p2 < P / 2; p2++) {
            ulonglong2 hv = *(const ulonglong2*)(hrow + 4 * p2); // LDS.128 bcast
            fma2(a0[2 * p2],     hv.x, w0);
            fma2(a0[2 * p2 + 1], hv.y, w0);
            fma2(a1[2 * p2],     hv.x, w1);
            fma2(a1[2 * p2 + 1], hv.y, w1);
        }
    }
}

template <int P, int L, int OFF>  // P even 2..12 token pairs; L,OFF per modality
__device__ __forceinline__ void run_chunk(
    float* hs, float* xs,
    const float* __restrict__ state,
    const float* __restrict__ W1ec,   // &W1[e][0][kh*256 + 2*tid], row stride HID
    float2 b1v,
    const float* __restrict__ W2ec,
    float2 init, int s0cb, int rem, int tid, int c0,
    float* __restrict__ pm)
{
    // ---- prologue: gather x (2P tokens, clamped pad) transposed into xs ----
    __syncthreads();
    #pragma unroll 1
    for (int idx = tid; idx < 2 * P * L; idx += 128) {
        int tk = idx / L, l = idx - tk * L;
        int slot = min(s0cb + tk, NTOK - 1);
        int tok = g_tokens[slot];
        xs[l * XSS + tk] = state[tok * DSTATE + OFF + l];
    }
    __syncthreads();

    {   // ---- h = relu(x . W1half + b1) for kk rows {2*tid, 2*tid+1} ----
        unsigned long long hA[P], hB[P];
        unsigned long long bA = splat2(b1v.x), bB = splat2(b1v.y);
        #pragma unroll
        for (int p = 0; p < P; p++) { hA[p] = bA; hB[p] = bB; }

        #pragma unroll 1
        for (int l0 = 0; l0 < L; l0 += 8) {
            float2 w[8];
            #pragma unroll
            for (int u = 0; u < 8; u++)
                w[u] = *(const float2*)(W1ec + (size_t)(l0 + u) * HID);
            #pragma unroll
            for (int u = 0; u < 8; u++) {
                unsigned long long w0 = splat2(w[u].x);
                unsigned long long w1 = splat2(w[u].y);
                const float* xrow = xs + (l0 + u) * XSS;
                #pragma unroll
                for (int p2 = 0; p2 < P / 2; p2++) {
                    ulonglong2 xv = *(const ulonglong2*)(xrow + 4 * p2); // bcast
                    fma2(hA[2 * p2],     xv.x, w0);
                    fma2(hA[2 * p2 + 1], xv.y, w0);
                    fma2(hB[2 * p2],     xv.x, w1);
                    fma2(hB[2 * p2 + 1], xv.y, w1);
                }
            }
        }
        // relu + store transposed rows
        float* rowA = hs + (2 * tid) * HSS;
        float* rowB = hs + (2 * tid + 1) * HSS;
        #pragma unroll
        for (int p = 0; p < P; p++) {
            float2 a = *(float2*)&hA[p];
            float2 b = *(float2*)&hB[p];
            a.x = fmaxf(a.x, 0.f); a.y = fmaxf(a.y, 0.f);
            b.x = fmaxf(b.x, 0.f); b.y = fmaxf(b.y, 0.f);
            *(float2*)&rowA[2 * p] = a;
            *(float2*)&rowB[2 * p] = b;
        }
    }
    __syncthreads();

    // ---- mainloop: W2 half stream, double-buffered ----
    unsigned long long a0[P], a1[P];
    unsigned long long i0 = splat2(init.x), i1 = splat2(init.y);
    #pragma unroll
    for (int p = 0; p < P; p++) { a0[p] = i0; a1[p] = i1; }

    float2 wA[WD], wB[WD];
    #pragma unroll
    for (int j = 0; j < WD; j++)
        wA[j] = __ldcs((const float2*)(W2ec + (size_t)j * EMB));

    #pragma unroll 1
    for (int g = 0; g < KC - 2 * WD; g += 2 * WD) {
        #pragma unroll
        for (int j = 0; j < WD; j++)
            wB[j] = __ldcs((const float2*)(W2ec + (size_t)(g + WD + j) * EMB));
        consume<P>(wA, hs, g, a0, a1);
        #pragma unroll
        for (int j = 0; j < WD; j++)
            wA[j] = __ldcs((const float2*)(W2ec + (size_t)(g + 2 * WD + j) * EMB));
        consume<P>(wB, hs, g + WD, a0, a1);
    }
    #pragma unroll
    for (int j = 0; j < WD; j++)
        wB[j] = __ldcs((const float2*)(W2ec + (size_t)(KC - WD + j) * EMB));
    consume<P>(wA, hs, KC - 2 * WD, a0, a1);
    consume<P>(wB, hs, KC - WD, a0, a1);

    // ---- epilogue: partials (slot-indexed; combine does slot->token) ----
    #pragma unroll
    for (int p = 0; p < P; p++) {
        float2 vA = *(float2*)&a0[p]; // col c0:   (tok 2p, tok 2p+1)
        float2 vB = *(float2*)&a1[p]; // col c0+1
        int t0 = 2 * p;
        if (t0 < rem) {
            int slot = s0cb + t0;
            *(float2*)&pm[(size_t)slot * EMB + c0] = make_float2(vA.x, vB.x);
        }
        if (t0 + 1 < rem) {
            int slot = s0cb + t0 + 1;
            *(float2*)&pm[(size_t)slot * EMB + c0] = make_float2(vA.y, vB.y);
        }
    }
}

template <int L, int OFF>
__device__ __forceinline__ void fused_body(const Params& p,
                                           const float* __restrict__ state,
                                           int m, int e, int kh, int tile, int tid,
                                           float* hs, float* xs) {
    int s0 = g_start[e];
    int n  = g_start[e + 1] - s0;
    if (n == 0) return;

    int c0 = tile * 256 + tid * 2;
    int j0 = kh * KC + 2 * tid;  // this thread's hidden cols (= hs rows)
    const float* W2ec = p.W2[m] + (size_t)e * HID * EMB + (size_t)kh * KC * EMB + c0;
    const float* W1ec = p.W1[m] + (size_t)e * L * HID + j0;
    float2 b1v = *(const float2*)&p.b1[m][e * HID + j0];
    float2 init = (kh == 0)
        ? make_float2(p.b2[m][e * EMB + c0]     + p.te[m][c0],
                      p.b2[m][e * EMB + c0 + 1] + p.te[m][c0 + 1])
        : make_float2(0.f, 0.f);
    float* pm = &g_part[kh][(size_t)m * NTOK * EMB];

    for (int cb = 0; cb < n; cb += CHT) {
        int rem = min(n - cb, CHT);
        int pairsEven = ((rem + 3) >> 2) << 1; // even ceil(rem/2)
        int s0cb = s0 + cb;
        switch (pairsEven) {
#define CASE(PP) case PP: run_chunk<PP, L, OFF>(hs, xs, state, W1ec, b1v, W2ec, init, s0cb, rem, tid, c0, pm); break;
            CASE(2) CASE(4) CASE(6) CASE(8) CASE(10) CASE(12)
#undef CASE
        }
    }
}

__global__ void __launch_bounds__(128, 4) k_fused(Params p,
                                                  const float* __restrict__ state) {
    int bx   = blockIdx.x;     // 0..7 = tile(0..3) | kh<<2
    int tile = bx & 3;
    int kh   = bx >> 2;        // k-half: W2 rows [kh*256, +256)
    int m    = blockIdx.y;     // 0..3
    int e    = blockIdx.z;     // 0..31
    int tid  = threadIdx.x;

    __shared__ __align__(16) float hs[KC * HSS];
    __shared__ __align__(16) float xs[64 * XSS];

    switch (m) {
        case 0: fused_body<64, 0  >(p, state, 0, e, kh, tile, tid, hs, xs); break;
        case 1: fused_body<64, 64 >(p, state, 1, e, kh, tile, tid, hs, xs); break;
        case 2: fused_body<32, 128>(p, state, 2, e, kh, tile, tid, hs, xs); break;
        case 3: fused_body<32, 160>(p, state, 3, e, kh, tile, tid, hs, xs); break;
    }
}

// ---------------------------------------------------------------------------
// Combine: out[tok][m][c] = part0 + part1, gathering slot -> token.
// ---------------------------------------------------------------------------
__global__ void __launch_bounds__(256) k_combine(float* __restrict__ out) {
    int slot = blockIdx.x;
    int m    = blockIdx.y;
    int tid  = threadIdx.x;
    int tok  = g_tokens[slot];
    const float4* p0 = (const float4*)(&g_part[0][0] + ((size_t)m * NTOK + slot) * EMB);
    const float4* p1 = (const float4*)(&g_part[1][0] + ((size_t)m * NTOK + slot) * EMB);
    float4* o = (float4*)(out + ((size_t)tok * 4 + m) * EMB);
    float4 a = p0[tid], b = p1[tid];
    o[tid] = make_float4(a.x + b.x, a.y + b.y, a.z + b.z, a.w + b.w);
}

// ---------------------------------------------------------------------------
extern "C" void kernel_launch(void* const* d_in, const int* in_sizes, int n_in,
                              void* d_out, int out_size) {
    const float* state = (const float*)d_in[0];
    const int*   ids   = (const int*)d_in[1];

    Params P;
    int base = 2;
    for (int m = 0; m < 4; m++) {
        P.W1[m] = (const float*)d_in[base + 0];
        P.b1[m] = (const float*)d_in[base + 1];
        P.W2[m] = (const float*)d_in[base + 2];
        P.b2[m] = (const float*)d_in[base + 3];
        P.te[m] = (const float*)d_in[base + 4];
        base += 5;
    }
    float* out = (float*)d_out;

    k_group<<<1, 512>>>(ids);
    k_fused<<<dim3(8, 4, 32), 128>>>(P, state);
    k_combine<<<dim3(NTOK, 4), 256>>>(out);
}